// round 10
// baseline (speedup 1.0000x reference)
#include <cuda_runtime.h>
#include <math.h>
#include <stdint.h>
#include <mma.h>

using namespace nvcuda;

// Problem constants
#define BB   2
#define SSQ  2048
#define HH   2048
#define NHH  16
#define HDD  128
#define H3   6144
#define BSR  4096
#define ALPHA 0.08838834764831845f

// Scratch
__device__ float g_qkv[(size_t)BSR * H3];
__device__ float g_ctx[(size_t)BSR * HH];

// ---------------------------------------------------------------------------
// Helpers
// ---------------------------------------------------------------------------
__device__ __forceinline__ uint32_t smem_u32(const void* p) {
    uint32_t a;
    asm("{ .reg .u64 t; cvta.to.shared.u64 t, %1; cvt.u32.u64 %0, t; }" : "=r"(a) : "l"(p));
    return a;
}
__device__ __forceinline__ void cp16(uint32_t dst, const void* src) {
    asm volatile("cp.async.cg.shared.global [%0], [%1], 16;" :: "r"(dst), "l"(src));
}
__device__ __forceinline__ float to_tf32(float x) {
    uint32_t u;
    asm("cvt.rna.tf32.f32 %0, %1;" : "=r"(u) : "f"(x));
    return __uint_as_float(u);
}

// ---------------------------------------------------------------------------
// WMMA tf32 GEMM: C[M,N] = A[M,K] @ W[K,N] + bias (+resid if EPI).
// W consumed directly (no pre-transpose): B tile [BK=32][132] row-major SMEM,
// B fragments row_major, RNA-rounded in-register (same numerics as before).
// CTA 128x128, 4 warps, 64x64 warp tile, double-buffered cp.async.
// ---------------------------------------------------------------------------
#define BM   128
#define BN   128
#define BK   32
#define BKP  40
#define BNP  132
#define ATILE_BYTES (128 * BKP * 4)          // 20480
#define BTILE_BYTES (BK * BNP * 4)           // 16896
#define STAGE_BYTES (ATILE_BYTES + BTILE_BYTES)
#define GEMM_SMEM   (2 * STAGE_BYTES)        // 74752 (epilogue reuses 64KB)

template <int EPI>
__global__ __launch_bounds__(128, 2)
void gemm_wmma(const float* __restrict__ A, const float* __restrict__ W,
               const float* __restrict__ bias, const float* __restrict__ resid,
               float* __restrict__ C, int N, int K) {
    extern __shared__ char smc[];
    const uint32_t sb = smem_u32(smc);
    const int tid = threadIdx.x;
    const int bm = blockIdx.y * BM;
    const int bn = blockIdx.x * BN;
    const int NS = K / BK;

    // A loads: 8 threads per 32-float row; 128 threads -> 16 rows/pass
    const int lrow = tid >> 3;           // 0..15
    const int lc4  = (tid & 7) << 2;     // 0..28
    // B loads: 32 threads per 128-float row; 128 threads -> 4 rows/pass
    const int brow = tid >> 5;           // 0..3
    const int bc4  = (tid & 31) << 2;    // 0..124

    const int warp = tid >> 5;
    const int wm = warp & 1;
    const int wn = warp >> 1;

    wmma::fragment<wmma::accumulator, 16, 16, 8, float> acc[4][4];
    #pragma unroll
    for (int i = 0; i < 4; i++)
        #pragma unroll
        for (int j = 0; j < 4; j++) wmma::fill_fragment(acc[i][j], 0.0f);

#define LOAD_STAGE(buf, s) do {                                               \
    const size_t koff_ = (size_t)(s) * BK;                                    \
    _Pragma("unroll")                                                         \
    for (int j_ = 0; j_ < 8; ++j_) {                                          \
        cp16(sb + (buf) * STAGE_BYTES + ((lrow + 16 * j_) * BKP + lc4) * 4,   \
             A + (size_t)(bm + lrow + 16 * j_) * K + koff_ + lc4);            \
    }                                                                         \
    _Pragma("unroll")                                                         \
    for (int j_ = 0; j_ < 8; ++j_) {                                          \
        cp16(sb + (buf) * STAGE_BYTES + ATILE_BYTES +                         \
                 ((brow + 4 * j_) * BNP + bc4) * 4,                           \
             W + (koff_ + brow + 4 * j_) * N + bn + bc4);                     \
    }                                                                         \
    asm volatile("cp.async.commit_group;" ::: "memory");                      \
} while (0)

    LOAD_STAGE(0, 0);

    for (int s = 0; s < NS; ++s) {
        if (s + 1 < NS) {
            LOAD_STAGE((s + 1) & 1, s + 1);
            asm volatile("cp.async.wait_group 1;" ::: "memory");
        } else {
            asm volatile("cp.async.wait_group 0;" ::: "memory");
        }
        __syncthreads();

        const float* As = (const float*)(smc + (s & 1) * STAGE_BYTES);
        const float* Bs = (const float*)(smc + (s & 1) * STAGE_BYTES + ATILE_BYTES);

        #pragma unroll
        for (int kk = 0; kk < BK / 8; ++kk) {
            const int k0 = kk * 8;
            wmma::fragment<wmma::matrix_a, 16, 16, 8, wmma::precision::tf32,
                           wmma::row_major> af[4];
            #pragma unroll
            for (int i = 0; i < 4; i++) {
                wmma::load_matrix_sync(af[i],
                    As + (wm * 64 + i * 16) * BKP + k0, BKP);
                #pragma unroll
                for (int e = 0; e < af[i].num_elements; e++)
                    af[i].x[e] = to_tf32(af[i].x[e]);
            }
            wmma::fragment<wmma::matrix_b, 16, 16, 8, wmma::precision::tf32,
                           wmma::row_major> bf[4];
            #pragma unroll
            for (int j = 0; j < 4; j++) {
                wmma::load_matrix_sync(bf[j],
                    Bs + k0 * BNP + wn * 64 + j * 16, BNP);
                #pragma unroll
                for (int e = 0; e < bf[j].num_elements; e++)
                    bf[j].x[e] = to_tf32(bf[j].x[e]);
            }

            #pragma unroll
            for (int i = 0; i < 4; i++)
                #pragma unroll
                for (int j = 0; j < 4; j++)
                    wmma::mma_sync(acc[i][j], af[i], bf[j], acc[i][j]);
        }
        __syncthreads();
    }

    float* esm = (float*)smc;
    #pragma unroll
    for (int i = 0; i < 4; i++)
        #pragma unroll
        for (int j = 0; j < 4; j++)
            wmma::store_matrix_sync(
                esm + (size_t)(wm * 64 + i * 16) * 128 + wn * 64 + j * 16,
                acc[i][j], 128, wmma::mem_row_major);
    __syncthreads();

    #pragma unroll
    for (int jj = 0; jj < 32; ++jj) {
        const int idx  = tid + 128 * jj;
        const int row  = idx >> 5;
        const int col4 = (idx & 31) << 2;
        float4 v = *(const float4*)(esm + row * 128 + col4);
        const float4 b4 = *(const float4*)(bias + bn + col4);
        v.x += b4.x; v.y += b4.y; v.z += b4.z; v.w += b4.w;
        if (EPI) {
            const float4 r4 = *(const float4*)(resid + (size_t)(bm + row) * N + bn + col4);
            v.x += r4.x; v.y += r4.y; v.z += r4.z; v.w += r4.w;
        }
        *(float4*)(C + (size_t)(bm + row) * N + bn + col4) = v;
    }
#undef LOAD_STAGE
}

// ---------------------------------------------------------------------------
// WMMA tf32 flash attention (R7 measured-best version, verbatim).
// CTA = (128-row Q tile, bh). 256 threads / 8 warps; warp owns 16 rows.
// ---------------------------------------------------------------------------
#define AQS 132
#define APS 68
#define ATTN_SMEM ((128 * AQS + 2 * 64 * AQS + 128 * APS + 128) * 4)

__global__ __launch_bounds__(256, 1)
void attn_wmma(const float* __restrict__ qkv, const float* __restrict__ alibi,
               float* __restrict__ ctx) {
    extern __shared__ float sm[];
    float* Qs   = sm;
    float* Ks   = sm + 128 * AQS;
    float* Vs   = sm + 192 * AQS;
    float* Ss   = sm + 256 * AQS;
    float* fRow = sm + 256 * AQS + 128 * APS;

    const uint32_t sb = smem_u32(sm);
    const uint32_t sbQ = sb;
    const uint32_t sbK = sb + 128 * AQS * 4;
    const uint32_t sbV = sb + 192 * AQS * 4;

    const int tid  = threadIdx.x;
    const int warp = tid >> 5;
    const int qt = (gridDim.x - 1) - blockIdx.x;
    const int bh = blockIdx.y;
    const int b  = bh >> 4;
    const int h  = bh & 15;
    const int q0 = qt * 128;

    const size_t base = (size_t)b * SSQ * H3 + (size_t)h * (3 * HDD);

    // discover accumulator lane->row mapping
    if (tid < 256) Ss[(tid >> 4) * APS + (tid & 15)] = (float)(tid >> 4);
    __syncthreads();
    int rid[8];
    {
        wmma::fragment<wmma::accumulator, 16, 16, 8, float> rmap;
        wmma::load_matrix_sync(rmap, Ss, APS, wmma::mem_row_major);
        #pragma unroll
        for (int e = 0; e < 8; e++) rid[e] = (int)rmap.x[e];
    }

    // issue Q loads (group)
    #pragma unroll
    for (int t = 0; t < 16; t++) {
        int idx = tid + 256 * t;
        int r2  = idx >> 5;
        int c4  = (idx & 31) << 2;
        cp16(sbQ + (r2 * AQS + c4) * 4,
             qkv + base + (size_t)(q0 + r2) * H3 + HDD + c4);
    }
    asm volatile("cp.async.commit_group;" ::: "memory");

    const int omr = warp * 16;
    wmma::fragment<wmma::accumulator, 16, 16, 8, float> oacc[8];
    #pragma unroll
    for (int j = 0; j < 8; j++) wmma::fill_fragment(oacc[j], 0.0f);

    const int r   = tid >> 1;
    const int hf  = tid & 1;
    const int c0s = hf * 32;
    float mrow = -INFINITY, lrow = 0.0f;

    const float* alib = alibi + (size_t)bh * SSQ;
    const int nkt = 2 * qt + 2;

    for (int kt = 0; kt < nkt; kt++) {
        const int k0 = kt * 64;
        __syncthreads();

        // issue K (group), then V (group)
        #pragma unroll
        for (int t = 0; t < 8; t++) {
            int idx = tid + 256 * t;
            int r2  = idx >> 5;
            int c4  = (idx & 31) << 2;
            cp16(sbK + (r2 * AQS + c4) * 4,
                 qkv + base + (size_t)(k0 + r2) * H3 + c4);
        }
        asm volatile("cp.async.commit_group;" ::: "memory");
        #pragma unroll
        for (int t = 0; t < 8; t++) {
            int idx = tid + 256 * t;
            int r2  = idx >> 5;
            int c4  = (idx & 31) << 2;
            cp16(sbV + (r2 * AQS + c4) * 4,
                 qkv + base + (size_t)(k0 + r2) * H3 + 2 * HDD + c4);
        }
        asm volatile("cp.async.commit_group;" ::: "memory");

        asm volatile("cp.async.wait_group 1;" ::: "memory");
        __syncthreads();

        // S = Q @ K^T : warp tile 16 x 64
        {
            wmma::fragment<wmma::accumulator, 16, 16, 8, float> sacc[4];
            #pragma unroll
            for (int j = 0; j < 4; j++) wmma::fill_fragment(sacc[j], 0.0f);
            #pragma unroll
            for (int ks = 0; ks < 16; ks++) {
                wmma::fragment<wmma::matrix_a, 16, 16, 8, wmma::precision::tf32,
                               wmma::row_major> af;
                wmma::load_matrix_sync(af, Qs + omr * AQS + ks * 8, AQS);
                #pragma unroll
                for (int j = 0; j < 4; j++) {
                    wmma::fragment<wmma::matrix_b, 16, 16, 8, wmma::precision::tf32,
                                   wmma::col_major> bf;
                    wmma::load_matrix_sync(bf, Ks + (j * 16) * AQS + ks * 8, AQS);
                    wmma::mma_sync(sacc[j], af, bf, sacc[j]);
                }
            }
            #pragma unroll
            for (int j = 0; j < 4; j++)
                wmma::store_matrix_sync(Ss + omr * APS + j * 16, sacc[j],
                                        APS, wmma::mem_row_major);
        }
        __syncthreads();

        // online softmax
        {
            float* srow = Ss + r * APS + c0s;
            float mt = -INFINITY;
            #pragma unroll
            for (int c = 0; c < 32; c++) {
                float v = srow[c] * ALPHA + alib[k0 + c0s + c];
                if (k0 + c0s + c > q0 + r) v = -INFINITY;
                srow[c] = v;
                mt = fmaxf(mt, v);
            }
            mt = fmaxf(mt, __shfl_xor_sync(0xffffffffu, mt, 1, 2));
            const float mn = fmaxf(mrow, mt);
            const float f  = __expf(mrow - mn);
            float ps = 0.0f;
            #pragma unroll
            for (int c = 0; c < 32; c++) {
                float p = __expf(srow[c] - mn);
                srow[c] = p;
                ps += p;
            }
            ps += __shfl_xor_sync(0xffffffffu, ps, 1, 2);
            lrow = lrow * f + ps;
            mrow = mn;
            if (hf == 0) fRow[r] = f;
        }
        asm volatile("cp.async.wait_group 0;" ::: "memory");
        __syncthreads();

        // rescale O, then O += P @ V
        {
            float fr[8];
            #pragma unroll
            for (int e = 0; e < 8; e++) fr[e] = fRow[omr + rid[e]];
            #pragma unroll
            for (int j = 0; j < 8; j++)
                #pragma unroll
                for (int e = 0; e < 8; e++) oacc[j].x[e] *= fr[e];

            #pragma unroll
            for (int ks = 0; ks < 8; ks++) {
                wmma::fragment<wmma::matrix_a, 16, 16, 8, wmma::precision::tf32,
                               wmma::row_major> af;
                wmma::load_matrix_sync(af, Ss + omr * APS + ks * 8, APS);
                #pragma unroll
                for (int j = 0; j < 8; j++) {
                    wmma::fragment<wmma::matrix_b, 16, 16, 8, wmma::precision::tf32,
                                   wmma::row_major> bf;
                    wmma::load_matrix_sync(bf, Vs + (ks * 8) * AQS + j * 16, AQS);
                    wmma::mma_sync(oacc[j], af, bf, oacc[j]);
                }
            }
        }
    }

    __syncthreads();
    #pragma unroll
    for (int j = 0; j < 8; j++)
        wmma::store_matrix_sync(Qs + omr * AQS + j * 16, oacc[j],
                                AQS, wmma::mem_row_major);
    __syncthreads();
    {
        const float inv = 1.0f / lrow;
        const int c0o = hf * 64;
        float* crow = ctx + ((size_t)b * SSQ + q0 + r) * HH + h * HDD + c0o;
        const float* orow = Qs + r * AQS + c0o;
        #pragma unroll
        for (int j = 0; j < 64; j += 4) {
            float4 o = *(const float4*)(orow + j);
            o.x *= inv; o.y *= inv; o.z *= inv; o.w *= inv;
            *(float4*)(crow + j) = o;
        }
    }
}

// ---------------------------------------------------------------------------
// Launch
// ---------------------------------------------------------------------------
extern "C" void kernel_launch(void* const* d_in, const int* in_sizes, int n_in,
                              void* d_out, int out_size) {
    (void)in_sizes; (void)n_in; (void)out_size;
    const float* hs    = (const float*)d_in[0];
    const float* resid = (const float*)d_in[2];
    const float* alibi = (const float*)d_in[3];
    const float* Wqkv  = (const float*)d_in[4];
    const float* bqkv  = (const float*)d_in[5];
    const float* Wd    = (const float*)d_in[6];
    const float* bd    = (const float*)d_in[7];
    float* out = (float*)d_out;

    float *qkvp, *ctxp;
    cudaGetSymbolAddress((void**)&qkvp, g_qkv);
    cudaGetSymbolAddress((void**)&ctxp, g_ctx);

    cudaFuncSetAttribute(gemm_wmma<0>, cudaFuncAttributeMaxDynamicSharedMemorySize, GEMM_SMEM);
    cudaFuncSetAttribute(gemm_wmma<1>, cudaFuncAttributeMaxDynamicSharedMemorySize, GEMM_SMEM);
    cudaFuncSetAttribute(attn_wmma,    cudaFuncAttributeMaxDynamicSharedMemorySize, ATTN_SMEM);

    // 1) qkv = hidden @ Wqkv + bqkv  (W consumed directly, no transpose)
    gemm_wmma<0><<<dim3(H3 / BN, BSR / BM), 128, GEMM_SMEM>>>(
        hs, Wqkv, bqkv, nullptr, qkvp, H3, HH);

    // 2) attention (R7 best)
    attn_wmma<<<dim3(SSQ / 128, BB * NHH), 256, ATTN_SMEM>>>(qkvp, alibi, ctxp);

    // 3) out = ctx @ Wd + bd + residual
    gemm_wmma<1><<<dim3(HH / BN, BSR / BM), 128, GEMM_SMEM>>>(
        ctxp, Wd, bd, resid, out, HH, HH);
}

// round 11
// speedup vs baseline: 1.0413x; 1.0413x over previous
#include <cuda_runtime.h>
#include <math.h>
#include <stdint.h>
#include <mma.h>

using namespace nvcuda;

// Problem constants
#define BB   2
#define SSQ  2048
#define HH   2048
#define NHH  16
#define HDD  128
#define H3   6144
#define BSR  4096
#define ALPHA 0.08838834764831845f

// Scratch
__device__ float g_qkv[(size_t)BSR * H3];
__device__ float g_ctx[(size_t)BSR * HH];
__device__ float g_wqkvt[(size_t)H3 * HH];
__device__ float g_wdt[(size_t)HH * HH];

// ---------------------------------------------------------------------------
// Helpers
// ---------------------------------------------------------------------------
__device__ __forceinline__ uint32_t smem_u32(const void* p) {
    uint32_t a;
    asm("{ .reg .u64 t; cvta.to.shared.u64 t, %1; cvt.u32.u64 %0, t; }" : "=r"(a) : "l"(p));
    return a;
}
__device__ __forceinline__ void cp16(uint32_t dst, const void* src) {
    asm volatile("cp.async.cg.shared.global [%0], [%1], 16;" :: "r"(dst), "l"(src));
}
__device__ __forceinline__ float to_tf32(float x) {
    uint32_t u;
    asm("cvt.rna.tf32.f32 %0, %1;" : "=r"(u) : "f"(x));
    return __uint_as_float(u);
}

// ---------------------------------------------------------------------------
// Transpose + round to tf32: Wt[n][k] = rna_tf32(W[k][n]).  W is [K][N].
// ---------------------------------------------------------------------------
__global__ __launch_bounds__(256)
void transpose_tf32(const float* __restrict__ W, float* __restrict__ Wt,
                    int K, int N) {
    __shared__ float t[32][33];
    const int nb = blockIdx.x * 32, kb = blockIdx.y * 32;
    const int tx = threadIdx.x & 31, ty = threadIdx.x >> 5;
    #pragma unroll
    for (int i = 0; i < 32; i += 8)
        t[ty + i][tx] = W[(size_t)(kb + ty + i) * N + nb + tx];
    __syncthreads();
    #pragma unroll
    for (int i = 0; i < 32; i += 8)
        Wt[(size_t)(nb + ty + i) * K + kb + tx] = to_tf32(t[tx][ty + i]);
}

// ---------------------------------------------------------------------------
// WMMA tf32 GEMM: CTA 128x128, 4 warps, 64x64 warp tile (R7 structure).
// BKP=36: conflict-free tf32 fragment loads (row bank bases all distinct),
// 144B rows keep 16B cp.async alignment.
// ---------------------------------------------------------------------------
#define BM   128
#define BN   128
#define BK   32
#define BKP  36
#define ATILE_BYTES (128 * BKP * 4)
#define STAGE_BYTES (2 * ATILE_BYTES)
#define GEMM_SMEM   (2 * STAGE_BYTES)

template <int EPI>
__global__ __launch_bounds__(128, 2)
void gemm_wmma(const float* __restrict__ A, const float* __restrict__ Wt,
               const float* __restrict__ bias, const float* __restrict__ resid,
               float* __restrict__ C, int N, int K) {
    extern __shared__ char smc[];
    const uint32_t sb = smem_u32(smc);
    const int tid = threadIdx.x;
    const int bm = blockIdx.y * BM;
    const int bn = blockIdx.x * BN;
    const int NS = K / BK;

    const int lrow = tid >> 3;
    const int lc4  = (tid & 7) << 2;

    const int warp = tid >> 5;
    const int wm = warp & 1;
    const int wn = warp >> 1;

    wmma::fragment<wmma::accumulator, 16, 16, 8, float> acc[4][4];
    #pragma unroll
    for (int i = 0; i < 4; i++)
        #pragma unroll
        for (int j = 0; j < 4; j++) wmma::fill_fragment(acc[i][j], 0.0f);

#define LOAD_STAGE(buf, s) do {                                               \
    const size_t koff_ = (size_t)(s) * BK;                                    \
    _Pragma("unroll")                                                         \
    for (int j_ = 0; j_ < 8; ++j_) {                                          \
        cp16(sb + (buf) * STAGE_BYTES + ((lrow + 16 * j_) * BKP + lc4) * 4,   \
             A + (size_t)(bm + lrow + 16 * j_) * K + koff_ + lc4);            \
    }                                                                         \
    _Pragma("unroll")                                                         \
    for (int j_ = 0; j_ < 8; ++j_) {                                          \
        cp16(sb + (buf) * STAGE_BYTES + ATILE_BYTES +                         \
                 ((lrow + 16 * j_) * BKP + lc4) * 4,                          \
             Wt + (size_t)(bn + lrow + 16 * j_) * K + koff_ + lc4);           \
    }                                                                         \
    asm volatile("cp.async.commit_group;" ::: "memory");                      \
} while (0)

    LOAD_STAGE(0, 0);

    for (int s = 0; s < NS; ++s) {
        if (s + 1 < NS) {
            LOAD_STAGE((s + 1) & 1, s + 1);
            asm volatile("cp.async.wait_group 1;" ::: "memory");
        } else {
            asm volatile("cp.async.wait_group 0;" ::: "memory");
        }
        __syncthreads();

        const float* As = (const float*)(smc + (s & 1) * STAGE_BYTES);
        const float* Bs = (const float*)(smc + (s & 1) * STAGE_BYTES + ATILE_BYTES);

        #pragma unroll
        for (int kk = 0; kk < BK / 8; ++kk) {
            const int k0 = kk * 8;
            wmma::fragment<wmma::matrix_a, 16, 16, 8, wmma::precision::tf32,
                           wmma::row_major> af[4];
            #pragma unroll
            for (int i = 0; i < 4; i++) {
                wmma::load_matrix_sync(af[i],
                    As + (wm * 64 + i * 16) * BKP + k0, BKP);
                #pragma unroll
                for (int e = 0; e < af[i].num_elements; e++)
                    af[i].x[e] = to_tf32(af[i].x[e]);
            }
            wmma::fragment<wmma::matrix_b, 16, 16, 8, wmma::precision::tf32,
                           wmma::col_major> bf[4];
            #pragma unroll
            for (int j = 0; j < 4; j++)
                wmma::load_matrix_sync(bf[j],
                    Bs + (wn * 64 + j * 16) * BKP + k0, BKP);

            #pragma unroll
            for (int i = 0; i < 4; i++)
                #pragma unroll
                for (int j = 0; j < 4; j++)
                    wmma::mma_sync(acc[i][j], af[i], bf[j], acc[i][j]);
        }
        __syncthreads();
    }

    float* esm = (float*)smc;
    #pragma unroll
    for (int i = 0; i < 4; i++)
        #pragma unroll
        for (int j = 0; j < 4; j++)
            wmma::store_matrix_sync(
                esm + (size_t)(wm * 64 + i * 16) * 128 + wn * 64 + j * 16,
                acc[i][j], 128, wmma::mem_row_major);
    __syncthreads();

    #pragma unroll
    for (int jj = 0; jj < 32; ++jj) {
        const int idx  = tid + 128 * jj;
        const int row  = idx >> 5;
        const int col4 = (idx & 31) << 2;
        float4 v = *(const float4*)(esm + row * 128 + col4);
        const float4 b4 = *(const float4*)(bias + bn + col4);
        v.x += b4.x; v.y += b4.y; v.z += b4.z; v.w += b4.w;
        if (EPI) {
            const float4 r4 = *(const float4*)(resid + (size_t)(bm + row) * N + bn + col4);
            v.x += r4.x; v.y += r4.y; v.z += r4.z; v.w += r4.w;
        }
        *(float4*)(C + (size_t)(bm + row) * N + bn + col4) = v;
    }
#undef LOAD_STAGE
}

// ---------------------------------------------------------------------------
// WMMA tf32 flash attention (R7 measured-best version, verbatim).
// ---------------------------------------------------------------------------
#define AQS 132
#define APS 68
#define ATTN_SMEM ((128 * AQS + 2 * 64 * AQS + 128 * APS + 128) * 4)

__global__ __launch_bounds__(256, 1)
void attn_wmma(const float* __restrict__ qkv, const float* __restrict__ alibi,
               float* __restrict__ ctx) {
    extern __shared__ float sm[];
    float* Qs   = sm;
    float* Ks   = sm + 128 * AQS;
    float* Vs   = sm + 192 * AQS;
    float* Ss   = sm + 256 * AQS;
    float* fRow = sm + 256 * AQS + 128 * APS;

    const uint32_t sb = smem_u32(sm);
    const uint32_t sbQ = sb;
    const uint32_t sbK = sb + 128 * AQS * 4;
    const uint32_t sbV = sb + 192 * AQS * 4;

    const int tid  = threadIdx.x;
    const int warp = tid >> 5;
    const int qt = (gridDim.x - 1) - blockIdx.x;
    const int bh = blockIdx.y;
    const int b  = bh >> 4;
    const int h  = bh & 15;
    const int q0 = qt * 128;

    const size_t base = (size_t)b * SSQ * H3 + (size_t)h * (3 * HDD);

    // discover accumulator lane->row mapping
    if (tid < 256) Ss[(tid >> 4) * APS + (tid & 15)] = (float)(tid >> 4);
    __syncthreads();
    int rid[8];
    {
        wmma::fragment<wmma::accumulator, 16, 16, 8, float> rmap;
        wmma::load_matrix_sync(rmap, Ss, APS, wmma::mem_row_major);
        #pragma unroll
        for (int e = 0; e < 8; e++) rid[e] = (int)rmap.x[e];
    }

    // issue Q loads (group)
    #pragma unroll
    for (int t = 0; t < 16; t++) {
        int idx = tid + 256 * t;
        int r2  = idx >> 5;
        int c4  = (idx & 31) << 2;
        cp16(sbQ + (r2 * AQS + c4) * 4,
             qkv + base + (size_t)(q0 + r2) * H3 + HDD + c4);
    }
    asm volatile("cp.async.commit_group;" ::: "memory");

    const int omr = warp * 16;
    wmma::fragment<wmma::accumulator, 16, 16, 8, float> oacc[8];
    #pragma unroll
    for (int j = 0; j < 8; j++) wmma::fill_fragment(oacc[j], 0.0f);

    const int r   = tid >> 1;
    const int hf  = tid & 1;
    const int c0s = hf * 32;
    float mrow = -INFINITY, lrow = 0.0f;

    const float* alib = alibi + (size_t)bh * SSQ;
    const int nkt = 2 * qt + 2;

    for (int kt = 0; kt < nkt; kt++) {
        const int k0 = kt * 64;
        __syncthreads();

        // issue K (group), then V (group)
        #pragma unroll
        for (int t = 0; t < 8; t++) {
            int idx = tid + 256 * t;
            int r2  = idx >> 5;
            int c4  = (idx & 31) << 2;
            cp16(sbK + (r2 * AQS + c4) * 4,
                 qkv + base + (size_t)(k0 + r2) * H3 + c4);
        }
        asm volatile("cp.async.commit_group;" ::: "memory");
        #pragma unroll
        for (int t = 0; t < 8; t++) {
            int idx = tid + 256 * t;
            int r2  = idx >> 5;
            int c4  = (idx & 31) << 2;
            cp16(sbV + (r2 * AQS + c4) * 4,
                 qkv + base + (size_t)(k0 + r2) * H3 + 2 * HDD + c4);
        }
        asm volatile("cp.async.commit_group;" ::: "memory");

        asm volatile("cp.async.wait_group 1;" ::: "memory");
        __syncthreads();

        // S = Q @ K^T : warp tile 16 x 64
        {
            wmma::fragment<wmma::accumulator, 16, 16, 8, float> sacc[4];
            #pragma unroll
            for (int j = 0; j < 4; j++) wmma::fill_fragment(sacc[j], 0.0f);
            #pragma unroll
            for (int ks = 0; ks < 16; ks++) {
                wmma::fragment<wmma::matrix_a, 16, 16, 8, wmma::precision::tf32,
                               wmma::row_major> af;
                wmma::load_matrix_sync(af, Qs + omr * AQS + ks * 8, AQS);
                #pragma unroll
                for (int j = 0; j < 4; j++) {
                    wmma::fragment<wmma::matrix_b, 16, 16, 8, wmma::precision::tf32,
                                   wmma::col_major> bf;
                    wmma::load_matrix_sync(bf, Ks + (j * 16) * AQS + ks * 8, AQS);
                    wmma::mma_sync(sacc[j], af, bf, sacc[j]);
                }
            }
            #pragma unroll
            for (int j = 0; j < 4; j++)
                wmma::store_matrix_sync(Ss + omr * APS + j * 16, sacc[j],
                                        APS, wmma::mem_row_major);
        }
        __syncthreads();

        // online softmax
        {
            float* srow = Ss + r * APS + c0s;
            float mt = -INFINITY;
            #pragma unroll
            for (int c = 0; c < 32; c++) {
                float v = srow[c] * ALPHA + alib[k0 + c0s + c];
                if (k0 + c0s + c > q0 + r) v = -INFINITY;
                srow[c] = v;
                mt = fmaxf(mt, v);
            }
            mt = fmaxf(mt, __shfl_xor_sync(0xffffffffu, mt, 1, 2));
            const float mn = fmaxf(mrow, mt);
            const float f  = __expf(mrow - mn);
            float ps = 0.0f;
            #pragma unroll
            for (int c = 0; c < 32; c++) {
                float p = __expf(srow[c] - mn);
                srow[c] = p;
                ps += p;
            }
            ps += __shfl_xor_sync(0xffffffffu, ps, 1, 2);
            lrow = lrow * f + ps;
            mrow = mn;
            if (hf == 0) fRow[r] = f;
        }
        asm volatile("cp.async.wait_group 0;" ::: "memory");
        __syncthreads();

        // rescale O, then O += P @ V
        {
            float fr[8];
            #pragma unroll
            for (int e = 0; e < 8; e++) fr[e] = fRow[omr + rid[e]];
            #pragma unroll
            for (int j = 0; j < 8; j++)
                #pragma unroll
                for (int e = 0; e < 8; e++) oacc[j].x[e] *= fr[e];

            #pragma unroll
            for (int ks = 0; ks < 8; ks++) {
                wmma::fragment<wmma::matrix_a, 16, 16, 8, wmma::precision::tf32,
                               wmma::row_major> af;
                wmma::load_matrix_sync(af, Ss + omr * APS + ks * 8, APS);
                #pragma unroll
                for (int j = 0; j < 8; j++) {
                    wmma::fragment<wmma::matrix_b, 16, 16, 8, wmma::precision::tf32,
                                   wmma::row_major> bf;
                    wmma::load_matrix_sync(bf, Vs + (ks * 8) * AQS + j * 16, AQS);
                    wmma::mma_sync(oacc[j], af, bf, oacc[j]);
                }
            }
        }
    }

    __syncthreads();
    #pragma unroll
    for (int j = 0; j < 8; j++)
        wmma::store_matrix_sync(Qs + omr * AQS + j * 16, oacc[j],
                                AQS, wmma::mem_row_major);
    __syncthreads();
    {
        const float inv = 1.0f / lrow;
        const int c0o = hf * 64;
        float* crow = ctx + ((size_t)b * SSQ + q0 + r) * HH + h * HDD + c0o;
        const float* orow = Qs + r * AQS + c0o;
        #pragma unroll
        for (int j = 0; j < 64; j += 4) {
            float4 o = *(const float4*)(orow + j);
            o.x *= inv; o.y *= inv; o.z *= inv; o.w *= inv;
            *(float4*)(crow + j) = o;
        }
    }
}

// ---------------------------------------------------------------------------
// Launch
// ---------------------------------------------------------------------------
extern "C" void kernel_launch(void* const* d_in, const int* in_sizes, int n_in,
                              void* d_out, int out_size) {
    (void)in_sizes; (void)n_in; (void)out_size;
    const float* hs    = (const float*)d_in[0];
    const float* resid = (const float*)d_in[2];
    const float* alibi = (const float*)d_in[3];
    const float* Wqkv  = (const float*)d_in[4];
    const float* bqkv  = (const float*)d_in[5];
    const float* Wd    = (const float*)d_in[6];
    const float* bd    = (const float*)d_in[7];
    float* out = (float*)d_out;

    float *qkvp, *ctxp, *wqkvt, *wdt;
    cudaGetSymbolAddress((void**)&qkvp,  g_qkv);
    cudaGetSymbolAddress((void**)&ctxp,  g_ctx);
    cudaGetSymbolAddress((void**)&wqkvt, g_wqkvt);
    cudaGetSymbolAddress((void**)&wdt,   g_wdt);

    cudaFuncSetAttribute(gemm_wmma<0>, cudaFuncAttributeMaxDynamicSharedMemorySize, GEMM_SMEM);
    cudaFuncSetAttribute(gemm_wmma<1>, cudaFuncAttributeMaxDynamicSharedMemorySize, GEMM_SMEM);
    cudaFuncSetAttribute(attn_wmma,    cudaFuncAttributeMaxDynamicSharedMemorySize, ATTN_SMEM);

    // 0) transpose + tf32-round weights
    transpose_tf32<<<dim3(H3 / 32, HH / 32), 256>>>(Wqkv, wqkvt, HH, H3);
    transpose_tf32<<<dim3(HH / 32, HH / 32), 256>>>(Wd,   wdt,   HH, HH);

    // 1) qkv = hidden @ Wqkv + bqkv
    gemm_wmma<0><<<dim3(H3 / BN, BSR / BM), 128, GEMM_SMEM>>>(
        hs, wqkvt, bqkv, nullptr, qkvp, H3, HH);

    // 2) attention (R7 best)
    attn_wmma<<<dim3(SSQ / 128, BB * NHH), 256, ATTN_SMEM>>>(qkvp, alibi, ctxp);

    // 3) out = ctx @ Wd + bd + residual
    gemm_wmma<1><<<dim3(HH / BN, BSR / BM), 128, GEMM_SMEM>>>(
        ctxp, wdt, bd, resid, out, HH, HH);
}

// round 12
// speedup vs baseline: 2.9995x; 2.8805x over previous
#include <cuda_runtime.h>
#include <cuda_fp16.h>
#include <math.h>
#include <stdint.h>
#include <mma.h>

using namespace nvcuda;

// Problem constants
#define BB   2
#define SSQ  2048
#define HH   2048
#define NHH  16
#define HDD  128
#define H3   6144
#define BSR  4096
#define ALPHA 0.08838834764831845f

// Scratch (all fp16)
__device__ __half g_hh[(size_t)BSR * HH];     // hidden as half
__device__ __half g_qkv[(size_t)BSR * H3];    // qkv as half
__device__ __half g_ctx[(size_t)BSR * HH];    // ctx as half
__device__ __half g_wqkvt[(size_t)H3 * HH];   // Wqkv^T half
__device__ __half g_wdt[(size_t)HH * HH];     // Wd^T half

// ---------------------------------------------------------------------------
// Helpers
// ---------------------------------------------------------------------------
__device__ __forceinline__ uint32_t smem_u32(const void* p) {
    uint32_t a;
    asm("{ .reg .u64 t; cvta.to.shared.u64 t, %1; cvt.u32.u64 %0, t; }" : "=r"(a) : "l"(p));
    return a;
}
__device__ __forceinline__ void cp16(uint32_t dst, const void* src) {
    asm volatile("cp.async.cg.shared.global [%0], [%1], 16;" :: "r"(dst), "l"(src));
}

// ---------------------------------------------------------------------------
// fp32 -> fp16 convert (vectorized)
// ---------------------------------------------------------------------------
__global__ __launch_bounds__(256)
void f2h(const float* __restrict__ in, __half* __restrict__ out, int n) {
    int i = (blockIdx.x * 256 + threadIdx.x) * 4;
    if (i < n) {
        float4 v = *(const float4*)(in + i);
        __half2 a = __floats2half2_rn(v.x, v.y);
        __half2 b = __floats2half2_rn(v.z, v.w);
        *(__half2*)(out + i)     = a;
        *(__half2*)(out + i + 2) = b;
    }
}

// ---------------------------------------------------------------------------
// Transpose + convert to half: Wt[n][k] = half(W[k][n]).  W is [K][N].
// ---------------------------------------------------------------------------
__global__ __launch_bounds__(256)
void transpose_h(const float* __restrict__ W, __half* __restrict__ Wt,
                 int K, int N) {
    __shared__ float t[32][33];
    const int nb = blockIdx.x * 32, kb = blockIdx.y * 32;
    const int tx = threadIdx.x & 31, ty = threadIdx.x >> 5;
    #pragma unroll
    for (int i = 0; i < 32; i += 8)
        t[ty + i][tx] = W[(size_t)(kb + ty + i) * N + nb + tx];
    __syncthreads();
    #pragma unroll
    for (int i = 0; i < 32; i += 8)
        Wt[(size_t)(nb + ty + i) * K + kb + tx] = __float2half(t[tx][ty + i]);
}

// ---------------------------------------------------------------------------
// WMMA fp16 GEMM: C = A @ Wt^T + bias (+resid). A,Wt half; accum fp32.
// CTA 128x128, 4 warps, 64x64 warp tile, BK=64 halves, double-buffered.
// MODE 0: C = half, bias only.  MODE 1: C = float, bias + resid.
// ---------------------------------------------------------------------------
#define BM   128
#define BN   128
#define GBK  64
#define BKH  72                               // padded stride (halves), 144 B
#define ATB  (128 * BKH * 2)                  // 18432 B
#define STB  (2 * ATB)                        // 36864 B per stage
#define GSMEM (2 * STB)                       // 73728 B (epilogue needs 65536)

template <int MODE>
__global__ __launch_bounds__(128, 2)
void gemm_h(const __half* __restrict__ A, const __half* __restrict__ Wt,
            const float* __restrict__ bias, const float* __restrict__ resid,
            void* __restrict__ Cv, int N, int K) {
    extern __shared__ char smc[];
    const uint32_t sb = smem_u32(smc);
    const int tid = threadIdx.x;
    const int bm = blockIdx.y * BM;
    const int bn = blockIdx.x * BN;
    const int NS = K / GBK;

    // loads: 8 threads per 64-half row (8x16B chunks); 16 rows per pass
    const int lrow = tid >> 3;           // 0..15
    const int lc8  = (tid & 7) << 3;     // 0,8,...,56 (halves)

    const int warp = tid >> 5;
    const int wm = warp & 1;
    const int wn = warp >> 1;

    wmma::fragment<wmma::accumulator, 16, 16, 16, float> acc[4][4];
    #pragma unroll
    for (int i = 0; i < 4; i++)
        #pragma unroll
        for (int j = 0; j < 4; j++) wmma::fill_fragment(acc[i][j], 0.0f);

#define LOAD_STAGE(buf, s) do {                                               \
    const size_t koff_ = (size_t)(s) * GBK;                                   \
    _Pragma("unroll")                                                         \
    for (int j_ = 0; j_ < 8; ++j_) {                                          \
        cp16(sb + (buf) * STB + ((lrow + 16 * j_) * BKH + lc8) * 2,           \
             A + (size_t)(bm + lrow + 16 * j_) * K + koff_ + lc8);            \
    }                                                                         \
    _Pragma("unroll")                                                         \
    for (int j_ = 0; j_ < 8; ++j_) {                                          \
        cp16(sb + (buf) * STB + ATB + ((lrow + 16 * j_) * BKH + lc8) * 2,     \
             Wt + (size_t)(bn + lrow + 16 * j_) * K + koff_ + lc8);           \
    }                                                                         \
    asm volatile("cp.async.commit_group;" ::: "memory");                      \
} while (0)

    LOAD_STAGE(0, 0);

    for (int s = 0; s < NS; ++s) {
        if (s + 1 < NS) {
            LOAD_STAGE((s + 1) & 1, s + 1);
            asm volatile("cp.async.wait_group 1;" ::: "memory");
        } else {
            asm volatile("cp.async.wait_group 0;" ::: "memory");
        }
        __syncthreads();

        const __half* As = (const __half*)(smc + (s & 1) * STB);
        const __half* Bs = (const __half*)(smc + (s & 1) * STB + ATB);

        #pragma unroll
        for (int kk = 0; kk < GBK / 16; ++kk) {
            const int k0 = kk * 16;
            wmma::fragment<wmma::matrix_a, 16, 16, 16, __half,
                           wmma::row_major> af[4];
            #pragma unroll
            for (int i = 0; i < 4; i++)
                wmma::load_matrix_sync(af[i],
                    As + (wm * 64 + i * 16) * BKH + k0, BKH);
            wmma::fragment<wmma::matrix_b, 16, 16, 16, __half,
                           wmma::col_major> bf[4];
            #pragma unroll
            for (int j = 0; j < 4; j++)
                wmma::load_matrix_sync(bf[j],
                    Bs + (wn * 64 + j * 16) * BKH + k0, BKH);

            #pragma unroll
            for (int i = 0; i < 4; i++)
                #pragma unroll
                for (int j = 0; j < 4; j++)
                    wmma::mma_sync(acc[i][j], af[i], bf[j], acc[i][j]);
        }
        __syncthreads();
    }

    // epilogue: stage fp32 through smem, coalesced writes
    float* esm = (float*)smc;
    #pragma unroll
    for (int i = 0; i < 4; i++)
        #pragma unroll
        for (int j = 0; j < 4; j++)
            wmma::store_matrix_sync(
                esm + (size_t)(wm * 64 + i * 16) * 128 + wn * 64 + j * 16,
                acc[i][j], 128, wmma::mem_row_major);
    __syncthreads();

    #pragma unroll
    for (int jj = 0; jj < 32; ++jj) {
        const int idx  = tid + 128 * jj;
        const int row  = idx >> 5;
        const int col4 = (idx & 31) << 2;
        float4 v = *(const float4*)(esm + row * 128 + col4);
        const float4 b4 = *(const float4*)(bias + bn + col4);
        v.x += b4.x; v.y += b4.y; v.z += b4.z; v.w += b4.w;
        if (MODE == 1) {
            const float4 r4 = *(const float4*)(resid + (size_t)(bm + row) * N + bn + col4);
            v.x += r4.x; v.y += r4.y; v.z += r4.z; v.w += r4.w;
            *(float4*)((float*)Cv + (size_t)(bm + row) * N + bn + col4) = v;
        } else {
            __half2 h0 = __floats2half2_rn(v.x, v.y);
            __half2 h1 = __floats2half2_rn(v.z, v.w);
            __half* cp = (__half*)Cv + (size_t)(bm + row) * N + bn + col4;
            *(__half2*)(cp)     = h0;
            *(__half2*)(cp + 2) = h1;
        }
    }
#undef LOAD_STAGE
}

// ---------------------------------------------------------------------------
// WMMA fp16 flash attention (R7 structure, half data, m16n16k16).
// CTA = (128-row Q tile, bh). 256 threads / 8 warps; warp owns 16 rows.
// SMEM: Qh[128][136] Kh[64][136] Vh[64][136] (half), Ss[128][68] f32,
//       Ph[128][72] half, fRow[128] f32  = 123392 B.
// O epilogue staged fp32 over the dead Q/K/V region (stride 132).
// ---------------------------------------------------------------------------
#define AQH 136
#define APS 68
#define PPH 72
#define OFF_K   34816
#define OFF_V   52224
#define OFF_S   69632
#define OFF_P   104448
#define OFF_F   122880
#define ATTN_SMEM 123392

__global__ __launch_bounds__(256, 1)
void attn_wmma(const __half* __restrict__ qkv, const float* __restrict__ alibi,
               __half* __restrict__ ctx) {
    extern __shared__ char smc[];
    __half* Qh   = (__half*)smc;
    __half* Kh   = (__half*)(smc + OFF_K);
    __half* Vh   = (__half*)(smc + OFF_V);
    float*  Ss   = (float*)(smc + OFF_S);
    __half* Ph   = (__half*)(smc + OFF_P);
    float*  fRow = (float*)(smc + OFF_F);
    float*  Of   = (float*)smc;               // epilogue staging, stride 132

    const uint32_t sb = smem_u32(smc);
    const uint32_t sbQ = sb;
    const uint32_t sbK = sb + OFF_K;
    const uint32_t sbV = sb + OFF_V;

    const int tid  = threadIdx.x;
    const int warp = tid >> 5;
    const int qt = (gridDim.x - 1) - blockIdx.x;   // descending work order
    const int bh = blockIdx.y;
    const int b  = bh >> 4;
    const int h  = bh & 15;
    const int q0 = qt * 128;

    const size_t base = (size_t)b * SSQ * H3 + (size_t)h * (3 * HDD);

    // discover fp32-accumulator lane->row mapping (m16n16k16)
    if (tid < 256) Ss[(tid >> 4) * APS + (tid & 15)] = (float)(tid >> 4);
    __syncthreads();
    int rid[8];
    {
        wmma::fragment<wmma::accumulator, 16, 16, 16, float> rmap;
        wmma::load_matrix_sync(rmap, Ss, APS, wmma::mem_row_major);
        #pragma unroll
        for (int e = 0; e < 8; e++) rid[e] = (int)rmap.x[e];
    }

    // issue Q loads (group): 128 rows x 16 chunks of 8 halves
    #pragma unroll
    for (int t = 0; t < 8; t++) {
        int idx = tid + 256 * t;
        int r2  = idx >> 4;
        int c8  = (idx & 15) << 3;
        cp16(sbQ + (r2 * AQH + c8) * 2,
             qkv + base + (size_t)(q0 + r2) * H3 + HDD + c8);
    }
    asm volatile("cp.async.commit_group;" ::: "memory");

    const int omr = warp * 16;
    wmma::fragment<wmma::accumulator, 16, 16, 16, float> oacc[8];
    #pragma unroll
    for (int j = 0; j < 8; j++) wmma::fill_fragment(oacc[j], 0.0f);

    const int r   = tid >> 1;
    const int hf  = tid & 1;
    const int c0s = hf * 32;
    float mrow = -INFINITY, lrow = 0.0f;

    const float* alib = alibi + (size_t)bh * SSQ;
    const int nkt = 2 * qt + 2;

    for (int kt = 0; kt < nkt; kt++) {
        const int k0 = kt * 64;
        __syncthreads();   // prior PV reads of Vh/Ph done; probe done (kt==0)

        // issue K (group), then V (group): 64 rows x 16 chunks
        #pragma unroll
        for (int t = 0; t < 4; t++) {
            int idx = tid + 256 * t;
            int r2  = idx >> 4;
            int c8  = (idx & 15) << 3;
            cp16(sbK + (r2 * AQH + c8) * 2,
                 qkv + base + (size_t)(k0 + r2) * H3 + c8);
        }
        asm volatile("cp.async.commit_group;" ::: "memory");
        #pragma unroll
        for (int t = 0; t < 4; t++) {
            int idx = tid + 256 * t;
            int r2  = idx >> 4;
            int c8  = (idx & 15) << 3;
            cp16(sbV + (r2 * AQH + c8) * 2,
                 qkv + base + (size_t)(k0 + r2) * H3 + 2 * HDD + c8);
        }
        asm volatile("cp.async.commit_group;" ::: "memory");

        asm volatile("cp.async.wait_group 1;" ::: "memory");   // Q+K ready
        __syncthreads();

        // S = Q @ K^T : warp tile 16 x 64, 8 k-steps of 16
        {
            wmma::fragment<wmma::accumulator, 16, 16, 16, float> sacc[4];
            #pragma unroll
            for (int j = 0; j < 4; j++) wmma::fill_fragment(sacc[j], 0.0f);
            #pragma unroll
            for (int ks = 0; ks < 8; ks++) {
                wmma::fragment<wmma::matrix_a, 16, 16, 16, __half,
                               wmma::row_major> af;
                wmma::load_matrix_sync(af, Qh + omr * AQH + ks * 16, AQH);
                #pragma unroll
                for (int j = 0; j < 4; j++) {
                    wmma::fragment<wmma::matrix_b, 16, 16, 16, __half,
                                   wmma::col_major> bf;
                    wmma::load_matrix_sync(bf, Kh + (j * 16) * AQH + ks * 16, AQH);
                    wmma::mma_sync(sacc[j], af, bf, sacc[j]);
                }
            }
            #pragma unroll
            for (int j = 0; j < 4; j++)
                wmma::store_matrix_sync(Ss + omr * APS + j * 16, sacc[j],
                                        APS, wmma::mem_row_major);
        }
        __syncthreads();

        // online softmax: thread (r, hf) owns cols hf*32..+31 of row r
        {
            float* srow = Ss + r * APS + c0s;
            __half* prow = Ph + r * PPH + c0s;
            float mt = -INFINITY;
            #pragma unroll
            for (int c = 0; c < 32; c++) {
                float v = srow[c] * ALPHA + alib[k0 + c0s + c];
                if (k0 + c0s + c > q0 + r) v = -INFINITY;
                srow[c] = v;
                mt = fmaxf(mt, v);
            }
            mt = fmaxf(mt, __shfl_xor_sync(0xffffffffu, mt, 1, 2));
            const float mn = fmaxf(mrow, mt);
            const float f  = __expf(mrow - mn);
            float ps = 0.0f;
            #pragma unroll
            for (int c = 0; c < 32; c++) {
                float p = __expf(srow[c] - mn);
                prow[c] = __float2half(p);
                ps += p;
            }
            ps += __shfl_xor_sync(0xffffffffu, ps, 1, 2);
            lrow = lrow * f + ps;
            mrow = mn;
            if (hf == 0) fRow[r] = f;
        }
        asm volatile("cp.async.wait_group 0;" ::: "memory");   // V ready
        __syncthreads();

        // rescale O, then O += P @ V (warp tile 16 x 128, 4 k-steps)
        {
            float fr[8];
            #pragma unroll
            for (int e = 0; e < 8; e++) fr[e] = fRow[omr + rid[e]];
            #pragma unroll
            for (int j = 0; j < 8; j++)
                #pragma unroll
                for (int e = 0; e < 8; e++) oacc[j].x[e] *= fr[e];

            #pragma unroll
            for (int ks = 0; ks < 4; ks++) {
                wmma::fragment<wmma::matrix_a, 16, 16, 16, __half,
                               wmma::row_major> af;
                wmma::load_matrix_sync(af, Ph + omr * PPH + ks * 16, PPH);
                #pragma unroll
                for (int j = 0; j < 8; j++) {
                    wmma::fragment<wmma::matrix_b, 16, 16, 16, __half,
                                   wmma::row_major> bf;
                    wmma::load_matrix_sync(bf, Vh + (ks * 16) * AQH + j * 16, AQH);
                    wmma::mma_sync(oacc[j], af, bf, oacc[j]);
                }
            }
        }
    }

    // spill O fp32 over dead Q/K/V region, normalize, write ctx (half)
    __syncthreads();
    #pragma unroll
    for (int j = 0; j < 8; j++)
        wmma::store_matrix_sync(Of + omr * 132 + j * 16, oacc[j],
                                132, wmma::mem_row_major);
    __syncthreads();
    {
        const float inv = 1.0f / lrow;
        const int c0o = hf * 64;
        __half* crow = ctx + ((size_t)b * SSQ + q0 + r) * HH + h * HDD + c0o;
        const float* orow = Of + r * 132 + c0o;
        #pragma unroll
        for (int j = 0; j < 64; j += 2) {
            __half2 hv = __floats2half2_rn(orow[j] * inv, orow[j + 1] * inv);
            *(__half2*)(crow + j) = hv;
        }
    }
}

// ---------------------------------------------------------------------------
// Launch
// ---------------------------------------------------------------------------
extern "C" void kernel_launch(void* const* d_in, const int* in_sizes, int n_in,
                              void* d_out, int out_size) {
    (void)in_sizes; (void)n_in; (void)out_size;
    const float* hs    = (const float*)d_in[0];
    const float* resid = (const float*)d_in[2];
    const float* alibi = (const float*)d_in[3];
    const float* Wqkv  = (const float*)d_in[4];
    const float* bqkv  = (const float*)d_in[5];
    const float* Wd    = (const float*)d_in[6];
    const float* bd    = (const float*)d_in[7];
    float* out = (float*)d_out;

    __half *hh, *qkvp, *ctxp, *wqkvt, *wdt;
    cudaGetSymbolAddress((void**)&hh,    g_hh);
    cudaGetSymbolAddress((void**)&qkvp,  g_qkv);
    cudaGetSymbolAddress((void**)&ctxp,  g_ctx);
    cudaGetSymbolAddress((void**)&wqkvt, g_wqkvt);
    cudaGetSymbolAddress((void**)&wdt,   g_wdt);

    cudaFuncSetAttribute(gemm_h<0>, cudaFuncAttributeMaxDynamicSharedMemorySize, GSMEM);
    cudaFuncSetAttribute(gemm_h<1>, cudaFuncAttributeMaxDynamicSharedMemorySize, GSMEM);
    cudaFuncSetAttribute(attn_wmma, cudaFuncAttributeMaxDynamicSharedMemorySize, ATTN_SMEM);

    // 0) convert hidden -> half; transpose+convert weights -> half
    f2h<<<(BSR * HH) / 1024, 256>>>(hs, hh, BSR * HH);
    transpose_h<<<dim3(H3 / 32, HH / 32), 256>>>(Wqkv, wqkvt, HH, H3);
    transpose_h<<<dim3(HH / 32, HH / 32), 256>>>(Wd,   wdt,   HH, HH);

    // 1) qkv = hidden @ Wqkv + bqkv  (fp16 in, half out)
    gemm_h<0><<<dim3(H3 / BN, BSR / BM), 128, GSMEM>>>(
        hh, wqkvt, bqkv, nullptr, qkvp, H3, HH);

    // 2) attention (fp16 flash)
    attn_wmma<<<dim3(SSQ / 128, BB * NHH), 256, ATTN_SMEM>>>(qkvp, alibi, ctxp);

    // 3) out = ctx @ Wd + bd + residual  (fp16 in, fp32 out)
    gemm_h<1><<<dim3(HH / BN, BSR / BM), 128, GSMEM>>>(
        ctxp, wdt, bd, resid, out, HH, HH);
}